// round 2
// baseline (speedup 1.0000x reference)
#include <cuda_runtime.h>
#include <math.h>
#include <stdint.h>

// ---------------------------------------------------------------------------
// FPLSTM layer: S=512, B=128, I=H=1024
//   pre = X @ Wx^T + bx                         (one big GEMM)
//   per step t (recurrence, persistent kernel):
//     gates = sigmoid(pre[t,:,:4H] + h @ Wh^T + bh)   (i,o,z,f)
//     m = z * tanh(c)
//     u = tanh(pre[t,:,4H:] + m @ Wum^T + bum)
//     c = i*u + f*c ;  h = o*tanh(c)
// Output: [S*B*H] outputs, then h_n [B*H], then c_n [B*H].
// GEMMs in tf32 mma.sync.m16n8k8 with fp32 accumulate.
// Only 3 kernel launches total => tiny CUDA graph (fixes 2MB upload leak).
// ---------------------------------------------------------------------------

namespace {
constexpr int SEQ  = 512;
constexpr int NB   = 128;
constexpr int K    = 1024;
constexpr int H    = 1024;
constexpr int NPRE = 5 * H;   // 5120
constexpr int NG   = 4 * H;   // 4096

constexpr int NCTA  = 128;          // persistent CTAs (1 per SM)
constexpr int GCOLS = NG / NCTA;    // 32 gate cols per CTA
constexpr int UCOLS = H / NCTA;     // 8 u cols per CTA
constexpr int LDW   = K + 4;        // padded weight stride (conflict-free bf LDS)
constexpr int LDA   = 20;           // padded A-stage stride
// dynamic smem layout (u32 words)
constexpr int OFF_WH = 0;
constexpr int OFF_WU = GCOLS * LDW;                 // 32896
constexpr int OFF_AS = (GCOLS + UCOLS) * LDW;       // 41120
constexpr int SMEM_WORDS = OFF_AS + NB * LDA;       // 43680 -> 174720 bytes
}

// Scratch (allocation-free __device__ globals)
__device__ __align__(16) float g_pre[(size_t)SEQ * NB * NPRE];
__device__ __align__(16) float g_h[NB * H];
__device__ __align__(16) float g_c[NB * H];
__device__ __align__(16) float g_gates[NB * NG];
__device__ __align__(16) float g_m[NB * H];
__device__ unsigned g_bar;

__device__ __forceinline__ uint32_t f2tf(float f) {
    uint32_t u;
    asm("cvt.rna.tf32.f32 %0, %1;" : "=r"(u) : "f"(f));
    return u;
}

__device__ __forceinline__ void mma_tf32(float* c, const uint32_t* a, const uint32_t* b) {
    asm volatile(
        "mma.sync.aligned.m16n8k8.row.col.f32.tf32.tf32.f32 "
        "{%0,%1,%2,%3}, {%4,%5,%6,%7}, {%8,%9}, {%0,%1,%2,%3};\n"
        : "+f"(c[0]), "+f"(c[1]), "+f"(c[2]), "+f"(c[3])
        : "r"(a[0]), "r"(a[1]), "r"(a[2]), "r"(a[3]),
          "r"(b[0]), "r"(b[1]));
}

__device__ __forceinline__ float sigmoidf_(float x) { return 1.0f / (1.0f + expf(-x)); }

// ---------------------------------------------------------------------------
// Phase A GEMM: pre = X @ Wx^T + bx   (M=65536, N=5120, K=1024)
// ---------------------------------------------------------------------------
template <int BM, int BN, int WM, int WN, int THREADS>
struct Gemm {
    static constexpr int BK = 16;
    static constexpr int LD = 20;
    static constexpr int MT = WM / 16;
    static constexpr int NT = WN / 8;
    static constexpr int WGN = BN / WN;
    static constexpr int WGM = BM / WM;
    static_assert(WGN * WGM * 32 == THREADS, "warp grid mismatch");
    static constexpr int SMEM_U32 = (BM + BN) * LD;

    __device__ static void run(const float* __restrict__ A,
                               const float* __restrict__ Bm,
                               float (&acc)[MT][NT][4],
                               uint32_t* __restrict__ sm) {
        uint32_t* As = sm;
        uint32_t* Bs = sm + BM * LD;
        const int tid  = threadIdx.x;
        const int lane = tid & 31;
        const int warp = tid >> 5;
        const int wm = warp / WGN;
        const int wn = warp % WGN;

        for (int kt = 0; kt < K; kt += BK) {
            #pragma unroll
            for (int i = tid; i < BM * 4; i += THREADS) {
                const int r  = i >> 2;
                const int cg = (i & 3) * 4;
                const float4 v = *reinterpret_cast<const float4*>(A + (size_t)r * K + kt + cg);
                uint4 d = make_uint4(f2tf(v.x), f2tf(v.y), f2tf(v.z), f2tf(v.w));
                *reinterpret_cast<uint4*>(As + r * LD + cg) = d;
            }
            #pragma unroll
            for (int i = tid; i < BN * 4; i += THREADS) {
                const int r  = i >> 2;
                const int cg = (i & 3) * 4;
                const float4 v = *reinterpret_cast<const float4*>(Bm + (size_t)r * K + kt + cg);
                uint4 d = make_uint4(f2tf(v.x), f2tf(v.y), f2tf(v.z), f2tf(v.w));
                *reinterpret_cast<uint4*>(Bs + r * LD + cg) = d;
            }
            __syncthreads();

            #pragma unroll
            for (int k8 = 0; k8 < BK / 8; ++k8) {
                uint32_t af[MT][4];
                uint32_t bf[NT][2];
                const int ar = lane >> 2;
                const int ac = k8 * 8 + (lane & 3);
                #pragma unroll
                for (int tm = 0; tm < MT; ++tm) {
                    const uint32_t* p = As + (wm * WM + tm * 16 + ar) * LD + ac;
                    af[tm][0] = p[0];
                    af[tm][1] = p[8 * LD];
                    af[tm][2] = p[4];
                    af[tm][3] = p[8 * LD + 4];
                }
                #pragma unroll
                for (int tn = 0; tn < NT; ++tn) {
                    const uint32_t* p = Bs + (wn * WN + tn * 8 + (lane >> 2)) * LD + ac;
                    bf[tn][0] = p[0];
                    bf[tn][1] = p[4];
                }
                #pragma unroll
                for (int tm = 0; tm < MT; ++tm)
                    #pragma unroll
                    for (int tn = 0; tn < NT; ++tn)
                        mma_tf32(&acc[tm][tn][0], af[tm], bf[tn]);
            }
            __syncthreads();
        }
    }
};

__global__ __launch_bounds__(256) void pre_kernel(const float* __restrict__ X,
                                                  const float* __restrict__ Wx,
                                                  const float* __restrict__ bx) {
    using G = Gemm<128, 128, 64, 32, 256>;
    __shared__ uint32_t sm[G::SMEM_U32];
    float acc[G::MT][G::NT][4] = {};

    const float* A  = X  + (size_t)blockIdx.y * 128 * K;
    const float* Bm = Wx + (size_t)blockIdx.x * 128 * K;
    G::run(A, Bm, acc, sm);

    const int lane = threadIdx.x & 31;
    const int warp = threadIdx.x >> 5;
    const int wm = warp / G::WGN;
    const int wn = warp % G::WGN;

    #pragma unroll
    for (int tm = 0; tm < G::MT; ++tm) {
        #pragma unroll
        for (int tn = 0; tn < G::NT; ++tn) {
            const int r0 = wm * 64 + tm * 16 + (lane >> 2);
            const int c0 = wn * 32 + tn * 8 + (lane & 3) * 2;
            #pragma unroll
            for (int j = 0; j < 4; ++j) {
                const int rr = r0 + (j >> 1) * 8;
                const int cc = c0 + (j & 1);
                const int gm = blockIdx.y * 128 + rr;
                const int gn = blockIdx.x * 128 + cc;
                g_pre[(size_t)gm * NPRE + gn] = acc[tm][tn][j] + bx[gn];
            }
        }
    }
}

// ---------------------------------------------------------------------------
// Persistent recurrence kernel. 128 CTAs x 256 threads, weights SMEM-resident.
// ---------------------------------------------------------------------------
__device__ __forceinline__ void grid_barrier(unsigned target) {
    __threadfence();
    __syncthreads();
    if (threadIdx.x == 0) {
        atomicAdd(&g_bar, 1u);
        while (*((volatile unsigned*)&g_bar) < target) { __nanosleep(32); }
    }
    __syncthreads();
}

// stage 128 x 16 fp32 -> tf32 into As (stride LDA), source row stride K
__device__ __forceinline__ void stageA(const float* __restrict__ g, int kt,
                                       uint32_t* __restrict__ As, int tid) {
    #pragma unroll
    for (int i = tid; i < NB * 4; i += 256) {
        const int r  = i >> 2;
        const int cg = (i & 3) * 4;
        const float4 v = *reinterpret_cast<const float4*>(g + (size_t)r * K + kt + cg);
        uint4 d = make_uint4(f2tf(v.x), f2tf(v.y), f2tf(v.z), f2tf(v.w));
        *reinterpret_cast<uint4*>(As + r * LDA + cg) = d;
    }
}

__global__ __launch_bounds__(256, 1) void lstm_kernel(const float* __restrict__ Wh,
                                                      const float* __restrict__ bh,
                                                      const float* __restrict__ Wum,
                                                      const float* __restrict__ bum,
                                                      float* __restrict__ out) {
    extern __shared__ uint32_t sm_u[];
    uint32_t* Wh_s = sm_u + OFF_WH;
    uint32_t* Wu_s = sm_u + OFF_WU;
    uint32_t* As   = sm_u + OFF_AS;

    const int tid  = threadIdx.x;
    const int lane = tid & 31;
    const int warp = tid >> 5;
    const int cta  = blockIdx.x;
    const int cBase = cta * GCOLS;        // gate col base (0..4095)
    const int uBase = cta * UCOLS;        // u col base (0..1023)
    const int gate  = cBase >> 10;        // 0:i 1:o 2:z 3:f

    // ---- preload weight slices (fp32 -> tf32, padded stride LDW) ----
    {
        const float* src = Wh + (size_t)cBase * K;
        for (int i = tid; i < GCOLS * (K / 4); i += 256) {
            const int r  = i / (K / 4);
            const int c4 = (i % (K / 4)) * 4;
            const float4 v = *reinterpret_cast<const float4*>(src + (size_t)r * K + c4);
            uint4 d = make_uint4(f2tf(v.x), f2tf(v.y), f2tf(v.z), f2tf(v.w));
            *reinterpret_cast<uint4*>(Wh_s + r * LDW + c4) = d;
        }
        const float* srcU = Wum + (size_t)uBase * K;
        for (int i = tid; i < UCOLS * (K / 4); i += 256) {
            const int r  = i / (K / 4);
            const int c4 = (i % (K / 4)) * 4;
            const float4 v = *reinterpret_cast<const float4*>(srcU + (size_t)r * K + c4);
            uint4 d = make_uint4(f2tf(v.x), f2tf(v.y), f2tf(v.z), f2tf(v.w));
            *reinterpret_cast<uint4*>(Wu_s + r * LDW + c4) = d;
        }
    }
    __syncthreads();

    // bias registers for epilogues
    unsigned bar_target = NCTA;

    for (int t = 0; t < SEQ; ++t) {
        // ================= Phase 1: gates = sigmoid(pre + h@Wh^T + bh) =========
        {
            // warp grid 4(M) x 2(N): WM=32 (MT=2), WN=16 (NT=2)
            const int wm = warp >> 1;
            const int wn = warp & 1;
            float acc[2][2][4] = {};

            for (int kt = 0; kt < K; kt += 16) {
                stageA(g_h, kt, As, tid);
                __syncthreads();
                #pragma unroll
                for (int k8 = 0; k8 < 2; ++k8) {
                    const int ar = lane >> 2;
                    const int ac = k8 * 8 + (lane & 3);
                    const int kk = kt + k8 * 8;
                    uint32_t af[2][4], bf[2][2];
                    #pragma unroll
                    for (int tm = 0; tm < 2; ++tm) {
                        const uint32_t* p = As + (wm * 32 + tm * 16 + ar) * LDA + ac;
                        af[tm][0] = p[0];
                        af[tm][1] = p[8 * LDA];
                        af[tm][2] = p[4];
                        af[tm][3] = p[8 * LDA + 4];
                    }
                    #pragma unroll
                    for (int tn = 0; tn < 2; ++tn) {
                        const uint32_t* p = Wh_s + (wn * 16 + tn * 8 + (lane >> 2)) * LDW + kk;
                        bf[tn][0] = p[lane & 3];
                        bf[tn][1] = p[4 + (lane & 3)];
                    }
                    #pragma unroll
                    for (int tm = 0; tm < 2; ++tm)
                        #pragma unroll
                        for (int tn = 0; tn < 2; ++tn)
                            mma_tf32(&acc[tm][tn][0], af[tm], bf[tn]);
                }
                __syncthreads();
            }

            // epilogue
            const float* pre_t = g_pre + (size_t)t * NB * NPRE;
            #pragma unroll
            for (int tm = 0; tm < 2; ++tm) {
                #pragma unroll
                for (int tn = 0; tn < 2; ++tn) {
                    #pragma unroll
                    for (int j = 0; j < 4; ++j) {
                        const int b = wm * 32 + tm * 16 + (lane >> 2) + 8 * (j >> 1);
                        const int n = cBase + wn * 16 + tn * 8 + (lane & 3) * 2 + (j & 1);
                        const float v = acc[tm][tn][j] + bh[n] + pre_t[(size_t)b * NPRE + n];
                        const float g = sigmoidf_(v);
                        if (gate == 2) {
                            const int jh = n & (H - 1);
                            g_m[b * H + jh] = g * tanhf(g_c[b * H + jh]);
                        } else {
                            g_gates[b * NG + n] = g;
                        }
                    }
                }
            }
        }
        grid_barrier(bar_target); bar_target += NCTA;

        // ================= Phase 2: u = tanh(pre_u + m@Wum^T + bum); update ====
        {
            // warp grid 8(M) x 1(N): each warp 16 rows x 8 cols (MT=1, NT=1)
            float acc2[4] = {};

            for (int kt = 0; kt < K; kt += 16) {
                stageA(g_m, kt, As, tid);
                __syncthreads();
                #pragma unroll
                for (int k8 = 0; k8 < 2; ++k8) {
                    const int ar = lane >> 2;
                    const int ac = k8 * 8 + (lane & 3);
                    const int kk = kt + k8 * 8;
                    uint32_t af[4], bf[2];
                    {
                        const uint32_t* p = As + (warp * 16 + ar) * LDA + ac;
                        af[0] = p[0];
                        af[1] = p[8 * LDA];
                        af[2] = p[4];
                        af[3] = p[8 * LDA + 4];
                    }
                    {
                        const uint32_t* p = Wu_s + (lane >> 2) * LDW + kk;
                        bf[0] = p[lane & 3];
                        bf[1] = p[4 + (lane & 3)];
                    }
                    mma_tf32(acc2, af, bf);
                }
                __syncthreads();
            }

            const float* preu = g_pre + (size_t)t * NB * NPRE + 4 * H;
            #pragma unroll
            for (int j = 0; j < 4; ++j) {
                const int b = warp * 16 + (lane >> 2) + 8 * (j >> 1);
                const int n = uBase + (lane & 3) * 2 + (j & 1);
                const float u  = tanhf(acc2[j] + bum[n] + preu[(size_t)b * NPRE + n]);
                const float ig = g_gates[b * NG + n];
                const float og = g_gates[b * NG + H + n];
                const float fg = g_gates[b * NG + 3 * H + n];
                const float cn = ig * u + fg * g_c[b * H + n];
                g_c[b * H + n] = cn;
                const float hv = og * tanhf(cn);
                g_h[b * H + n] = hv;
                out[(size_t)t * NB * H + b * H + n] = hv;
                if (t == SEQ - 1) {
                    out[(size_t)SEQ * NB * H + b * H + n] = hv;
                    out[(size_t)SEQ * NB * H + NB * H + b * H + n] = cn;
                }
            }
        }
        grid_barrier(bar_target); bar_target += NCTA;
    }
}

__global__ void init_kernel() {
    const int i = blockIdx.x * blockDim.x + threadIdx.x;
    if (i == 0) g_bar = 0u;
    if (i < NB * H) {
        g_h[i] = 0.0f;
        g_c[i] = 0.0f;
    }
}

extern "C" void kernel_launch(void* const* d_in, const int* in_sizes, int n_in,
                              void* d_out, int out_size) {
    (void)in_sizes; (void)n_in; (void)out_size;
    const float* X   = (const float*)d_in[0];
    const float* Wx  = (const float*)d_in[1];
    const float* bx  = (const float*)d_in[2];
    const float* Wh  = (const float*)d_in[3];
    const float* bh  = (const float*)d_in[4];
    const float* Wum = (const float*)d_in[5];
    const float* bum = (const float*)d_in[6];
    float* out = (float*)d_out;

    static_assert(SMEM_WORDS * 4 == 174720, "smem layout");
    cudaFuncSetAttribute(lstm_kernel, cudaFuncAttributeMaxDynamicSharedMemorySize,
                         SMEM_WORDS * 4);

    init_kernel<<<(NB * H + 255) / 256, 256>>>();
    pre_kernel<<<dim3(NPRE / 128, (SEQ * NB) / 128), 256>>>(X, Wx, bx);
    lstm_kernel<<<NCTA, 256, SMEM_WORDS * 4>>>(Wh, bh, Wum, bum, out);
}

// round 3
// speedup vs baseline: 1.6796x; 1.6796x over previous
#include <cuda_runtime.h>
#include <math.h>
#include <stdint.h>

// ---------------------------------------------------------------------------
// FPLSTM layer: S=512, B=128, I=H=1024
//   pre = X @ Wx^T + bx                         (one big GEMM)
//   per step t (persistent kernel, 128 CTAs):
//     gates = sigmoid(pre[t,:,:4H] + h @ Wh^T + bh)   (i,o,z,f)
//     m = z * tanh(c)
//     u = tanh(pre[t,:,4H:] + m @ Wum^T + bum)
//     c = i*u + f*c ;  h = o*tanh(c)
// Each CTA owns 8 h-columns: all 4 gate slices + u slice + c state stay local.
// Only m (and h via `out`) round-trips through L2. Single-sync double-buffered
// A staging pipelines L2 latency under the MMAs.
// ---------------------------------------------------------------------------

namespace {
constexpr int SEQ  = 512;
constexpr int NB   = 128;
constexpr int K    = 1024;
constexpr int H    = 1024;
constexpr int NPRE = 5 * H;   // 5120

constexpr int NCTA  = 128;
constexpr int UCOLS = H / NCTA;       // 8 owned h-columns per CTA
constexpr int LDW   = K + 4;          // padded weight stride
constexpr int BK    = 32;
constexpr int LDA   = BK + 4;         // 36
constexpr int ABUF  = NB * LDA;       // 4608 words per A buffer
// dynamic smem layout (u32 words)
constexpr int OFF_W   = 0;                    // 40 rows x LDW (Wh 32 + Wum 8)
constexpr int OFF_AS  = 40 * LDW;             // 41120
constexpr int OFF_IOF = OFF_AS + 2 * ABUF;    // 50336 : [3][128][8] floats
constexpr int OFF_C   = OFF_IOF + 3 * NB * UCOLS; // 53408 : [128][8] floats
constexpr int SMEM_WORDS = OFF_C + NB * UCOLS;    // 54432 -> 217728 bytes
}

// Scratch (allocation-free __device__ globals)
__device__ __align__(16) float g_pre[(size_t)SEQ * NB * NPRE];
__device__ __align__(16) float g_m[NB * H];
__device__ unsigned g_bar;

__device__ __forceinline__ uint32_t f2tf(float f) {
    uint32_t u;
    asm("cvt.rna.tf32.f32 %0, %1;" : "=r"(u) : "f"(f));
    return u;
}

__device__ __forceinline__ void mma_tf32(float* c, const uint32_t* a, const uint32_t* b) {
    asm volatile(
        "mma.sync.aligned.m16n8k8.row.col.f32.tf32.tf32.f32 "
        "{%0,%1,%2,%3}, {%4,%5,%6,%7}, {%8,%9}, {%0,%1,%2,%3};\n"
        : "+f"(c[0]), "+f"(c[1]), "+f"(c[2]), "+f"(c[3])
        : "r"(a[0]), "r"(a[1]), "r"(a[2]), "r"(a[3]),
          "r"(b[0]), "r"(b[1]));
}

__device__ __forceinline__ float fast_sigmoid(float x) {
    return __fdividef(1.0f, 1.0f + __expf(-x));
}
__device__ __forceinline__ float fast_tanh(float x) {
    // 1 - 2/(e^{2x}+1): saturates correctly at +/-1 for large |x|
    return 1.0f - __fdividef(2.0f, __expf(2.0f * x) + 1.0f);
}

// ---------------------------------------------------------------------------
// Phase A GEMM: pre = X @ Wx^T + bx   (unchanged from round 2)
// ---------------------------------------------------------------------------
template <int BM, int BN, int WM, int WN, int THREADS>
struct Gemm {
    static constexpr int TBK = 16;
    static constexpr int LD = 20;
    static constexpr int MT = WM / 16;
    static constexpr int NT = WN / 8;
    static constexpr int WGN = BN / WN;
    static constexpr int WGM = BM / WM;
    static_assert(WGN * WGM * 32 == THREADS, "warp grid mismatch");
    static constexpr int SMEM_U32 = (BM + BN) * LD;

    __device__ static void run(const float* __restrict__ A,
                               const float* __restrict__ Bm,
                               float (&acc)[MT][NT][4],
                               uint32_t* __restrict__ sm) {
        uint32_t* As = sm;
        uint32_t* Bs = sm + BM * LD;
        const int tid  = threadIdx.x;
        const int lane = tid & 31;
        const int warp = tid >> 5;
        const int wm = warp / WGN;
        const int wn = warp % WGN;

        for (int kt = 0; kt < K; kt += TBK) {
            #pragma unroll
            for (int i = tid; i < BM * 4; i += THREADS) {
                const int r  = i >> 2;
                const int cg = (i & 3) * 4;
                const float4 v = *reinterpret_cast<const float4*>(A + (size_t)r * K + kt + cg);
                uint4 d = make_uint4(f2tf(v.x), f2tf(v.y), f2tf(v.z), f2tf(v.w));
                *reinterpret_cast<uint4*>(As + r * LD + cg) = d;
            }
            #pragma unroll
            for (int i = tid; i < BN * 4; i += THREADS) {
                const int r  = i >> 2;
                const int cg = (i & 3) * 4;
                const float4 v = *reinterpret_cast<const float4*>(Bm + (size_t)r * K + kt + cg);
                uint4 d = make_uint4(f2tf(v.x), f2tf(v.y), f2tf(v.z), f2tf(v.w));
                *reinterpret_cast<uint4*>(Bs + r * LD + cg) = d;
            }
            __syncthreads();

            #pragma unroll
            for (int k8 = 0; k8 < TBK / 8; ++k8) {
                uint32_t af[MT][4];
                uint32_t bf[NT][2];
                const int ar = lane >> 2;
                const int ac = k8 * 8 + (lane & 3);
                #pragma unroll
                for (int tm = 0; tm < MT; ++tm) {
                    const uint32_t* p = As + (wm * WM + tm * 16 + ar) * LD + ac;
                    af[tm][0] = p[0];
                    af[tm][1] = p[8 * LD];
                    af[tm][2] = p[4];
                    af[tm][3] = p[8 * LD + 4];
                }
                #pragma unroll
                for (int tn = 0; tn < NT; ++tn) {
                    const uint32_t* p = Bs + (wn * WN + tn * 8 + (lane >> 2)) * LD + ac;
                    bf[tn][0] = p[0];
                    bf[tn][1] = p[4];
                }
                #pragma unroll
                for (int tm = 0; tm < MT; ++tm)
                    #pragma unroll
                    for (int tn = 0; tn < NT; ++tn)
                        mma_tf32(&acc[tm][tn][0], af[tm], bf[tn]);
            }
            __syncthreads();
        }
    }
};

__global__ __launch_bounds__(256) void pre_kernel(const float* __restrict__ X,
                                                  const float* __restrict__ Wx,
                                                  const float* __restrict__ bx) {
    using G = Gemm<128, 128, 64, 32, 256>;
    __shared__ uint32_t sm[G::SMEM_U32];
    float acc[G::MT][G::NT][4] = {};

    const float* A  = X  + (size_t)blockIdx.y * 128 * K;
    const float* Bm = Wx + (size_t)blockIdx.x * 128 * K;
    G::run(A, Bm, acc, sm);

    const int lane = threadIdx.x & 31;
    const int warp = threadIdx.x >> 5;
    const int wm = warp / G::WGN;
    const int wn = warp % G::WGN;

    #pragma unroll
    for (int tm = 0; tm < G::MT; ++tm) {
        #pragma unroll
        for (int tn = 0; tn < G::NT; ++tn) {
            const int r0 = wm * 64 + tm * 16 + (lane >> 2);
            const int c0 = wn * 32 + tn * 8 + (lane & 3) * 2;
            #pragma unroll
            for (int j = 0; j < 4; ++j) {
                const int rr = r0 + (j >> 1) * 8;
                const int cc = c0 + (j & 1);
                const int gm = blockIdx.y * 128 + rr;
                const int gn = blockIdx.x * 128 + cc;
                g_pre[(size_t)gm * NPRE + gn] = acc[tm][tn][j] + bx[gn];
            }
        }
    }
}

// ---------------------------------------------------------------------------
// Persistent recurrence kernel
// ---------------------------------------------------------------------------
__device__ __forceinline__ void grid_barrier(unsigned target) {
    __threadfence();
    __syncthreads();
    if (threadIdx.x == 0) {
        atomicAdd(&g_bar, 1u);
        while (*((volatile unsigned*)&g_bar) < target) { __nanosleep(16); }
    }
    __syncthreads();
}

// load a 128 x BK tile (row stride K) into 4 float4 regs per thread (L2-only)
__device__ __forceinline__ void stage_load(const float* __restrict__ g, int kt,
                                           float4 (&v)[4], int tid) {
    #pragma unroll
    for (int k = 0; k < 4; ++k) {
        const int i = tid + k * 256;
        const int r = i >> 3;
        const int c4 = (i & 7) * 4;
        v[k] = __ldcg(reinterpret_cast<const float4*>(g + (size_t)r * K + kt + c4));
    }
}
__device__ __forceinline__ void stage_store(uint32_t* __restrict__ dst,
                                            const float4 (&v)[4], int tid) {
    #pragma unroll
    for (int k = 0; k < 4; ++k) {
        const int i = tid + k * 256;
        const int r = i >> 3;
        const int c4 = (i & 7) * 4;
        uint4 d = make_uint4(f2tf(v[k].x), f2tf(v[k].y), f2tf(v[k].z), f2tf(v[k].w));
        *reinterpret_cast<uint4*>(dst + r * LDA + c4) = d;
    }
}

__global__ __launch_bounds__(256, 1) void lstm_kernel(const float* __restrict__ Wh,
                                                      const float* __restrict__ bh,
                                                      const float* __restrict__ Wum,
                                                      const float* __restrict__ bum,
                                                      float* __restrict__ out) {
    extern __shared__ uint32_t sm_u[];
    uint32_t* W_s   = sm_u + OFF_W;      // rows 0..31: Wh (i,o,z,f x 8 cols); 32..39: Wum
    uint32_t* As    = sm_u + OFF_AS;     // 2 x ABUF
    float*    iof_s = reinterpret_cast<float*>(sm_u + OFF_IOF);  // [3][128][8]
    float*    c_s   = reinterpret_cast<float*>(sm_u + OFF_C);    // [128][8]

    const int tid   = threadIdx.x;
    const int lane  = tid & 31;
    const int warp  = tid >> 5;
    const int uBase = blockIdx.x * UCOLS;

    // ---- preload weight slices (fp32 -> tf32) ----
    for (int i = tid; i < 40 * 256; i += 256) {
        const int row = i >> 8;          // 0..39 (uniform per iteration)
        const int c4  = (i & 255) * 4;
        const float* src;
        if (row < 32) {
            const int g = row >> 3, r = row & 7;
            src = Wh + (size_t)(g * H + uBase + r) * K;
        } else {
            src = Wum + (size_t)(uBase + (row - 32)) * K;
        }
        const float4 v = *reinterpret_cast<const float4*>(src + c4);
        uint4 d = make_uint4(f2tf(v.x), f2tf(v.y), f2tf(v.z), f2tf(v.w));
        *reinterpret_cast<uint4*>(W_s + row * LDW + c4) = d;
    }
    // zero c state
    for (int i = tid; i < NB * UCOLS; i += 256) c_s[i] = 0.0f;
    __syncthreads();

    // phase-1 warp layout: wm in [0,4) covers 32 batch rows; wn in [0,2) covers 16 gate-cols
    const int wm = warp >> 1;
    const int wn = warp & 1;
    const int ar = lane >> 2;
    const int aq = lane & 3;

    // register-resident biases
    float bhreg[2][2];   // [tn][jb] : gate col gi = wn*16 + tn*8 + aq*2 + jb
    #pragma unroll
    for (int tn = 0; tn < 2; ++tn)
        #pragma unroll
        for (int jb = 0; jb < 2; ++jb) {
            const int gi = wn * 16 + tn * 8 + aq * 2 + jb;
            bhreg[tn][jb] = bh[(gi >> 3) * H + uBase + (gi & 7)];
        }
    float2 bureg = *reinterpret_cast<const float2*>(bum + uBase + aq * 2);

    unsigned bar_target = NCTA;

    for (int t = 0; t < SEQ; ++t) {
        const float* pre_t = g_pre + (size_t)t * NB * NPRE;

        // ================= Phase 1: gates =================
        {
            // prefetch pre slices (consumed at epilogue, ~32 tiles of latency cover)
            float2 pre2[2][2][2];   // [tm][jh][tn]
            #pragma unroll
            for (int tm = 0; tm < 2; ++tm)
                #pragma unroll
                for (int jh = 0; jh < 2; ++jh)
                    #pragma unroll
                    for (int tn = 0; tn < 2; ++tn) {
                        const int b = wm * 32 + tm * 16 + ar + 8 * jh;
                        const int g = wn * 2 + tn;
                        pre2[tm][jh][tn] = __ldcg(reinterpret_cast<const float2*>(
                            pre_t + (size_t)b * NPRE + g * H + uBase + aq * 2));
                    }

            float acc[2][2][4] = {};
            if (t > 0) {
                const float* hsrc = out + (size_t)(t - 1) * NB * H;
                float4 v[4];
                stage_load(hsrc, 0, v, tid);
                stage_store(As, v, tid);
                __syncthreads();
                int p = 0;
                #pragma unroll 1
                for (int kt = 0; kt < K / BK; ++kt) {
                    const bool more = (kt + 1 < K / BK);
                    if (more) stage_load(hsrc, (kt + 1) * BK, v, tid);
                    const uint32_t* cur = As + p * ABUF;
                    #pragma unroll
                    for (int k8 = 0; k8 < BK / 8; ++k8) {
                        const int ac = k8 * 8 + aq;
                        uint32_t af[2][4], bf[2][2];
                        #pragma unroll
                        for (int tm = 0; tm < 2; ++tm) {
                            const uint32_t* pp = cur + (wm * 32 + tm * 16 + ar) * LDA + ac;
                            af[tm][0] = pp[0];
                            af[tm][1] = pp[8 * LDA];
                            af[tm][2] = pp[4];
                            af[tm][3] = pp[8 * LDA + 4];
                        }
                        #pragma unroll
                        for (int tn = 0; tn < 2; ++tn) {
                            const uint32_t* q = W_s + (wn * 16 + tn * 8 + ar) * LDW
                                              + kt * BK + k8 * 8 + aq;
                            bf[tn][0] = q[0];
                            bf[tn][1] = q[4];
                        }
                        #pragma unroll
                        for (int tm = 0; tm < 2; ++tm)
                            #pragma unroll
                            for (int tn = 0; tn < 2; ++tn)
                                mma_tf32(&acc[tm][tn][0], af[tm], bf[tn]);
                    }
                    if (more) stage_store(As + (p ^ 1) * ABUF, v, tid);
                    __syncthreads();
                    p ^= 1;
                }
            }

            // epilogue: sigmoid; i/o/f -> smem, z -> m -> global
            #pragma unroll
            for (int tm = 0; tm < 2; ++tm) {
                #pragma unroll
                for (int tn = 0; tn < 2; ++tn) {
                    const int g = wn * 2 + tn;              // warp-uniform
                    #pragma unroll
                    for (int j = 0; j < 4; ++j) {
                        const int jb = j & 1, jh = j >> 1;
                        const int b  = wm * 32 + tm * 16 + ar + 8 * jh;
                        const int col = aq * 2 + jb;
                        const float pv = jb ? pre2[tm][jh][tn].y : pre2[tm][jh][tn].x;
                        const float s = fast_sigmoid(acc[tm][tn][j] + bhreg[tn][jb] + pv);
                        if (g == 2) {
                            const float mm = s * fast_tanh(c_s[b * UCOLS + col]);
                            g_m[b * H + uBase + col] = mm;
                        } else {
                            const int slot = (g == 3) ? 2 : g;   // i->0, o->1, f->2
                            iof_s[slot * (NB * UCOLS) + b * UCOLS + col] = s;
                        }
                    }
                }
            }
        }
        grid_barrier(bar_target); bar_target += NCTA;

        // ================= Phase 2: u + state update =================
        {
            float2 preu2[2];    // [jh]
            #pragma unroll
            for (int jh = 0; jh < 2; ++jh) {
                const int b = warp * 16 + ar + 8 * jh;
                preu2[jh] = __ldcg(reinterpret_cast<const float2*>(
                    pre_t + (size_t)b * NPRE + 4 * H + uBase + aq * 2));
            }

            float acc2[4] = {};
            if (t > 0) {
                float4 v[4];
                stage_load(g_m, 0, v, tid);
                stage_store(As, v, tid);
                __syncthreads();
                int p = 0;
                #pragma unroll 1
                for (int kt = 0; kt < K / BK; ++kt) {
                    const bool more = (kt + 1 < K / BK);
                    if (more) stage_load(g_m, (kt + 1) * BK, v, tid);
                    const uint32_t* cur = As + p * ABUF;
                    #pragma unroll
                    for (int k8 = 0; k8 < BK / 8; ++k8) {
                        const int ac = k8 * 8 + aq;
                        uint32_t af[4], bf[2];
                        const uint32_t* pp = cur + (warp * 16 + ar) * LDA + ac;
                        af[0] = pp[0];
                        af[1] = pp[8 * LDA];
                        af[2] = pp[4];
                        af[3] = pp[8 * LDA + 4];
                        const uint32_t* q = W_s + (32 + ar) * LDW + kt * BK + k8 * 8 + aq;
                        bf[0] = q[0];
                        bf[1] = q[4];
                        mma_tf32(acc2, af, bf);
                    }
                    if (more) stage_store(As + (p ^ 1) * ABUF, v, tid);
                    __syncthreads();
                    p ^= 1;
                }
            }

            #pragma unroll
            for (int j = 0; j < 4; ++j) {
                const int jb = j & 1, jh = j >> 1;
                const int b   = warp * 16 + ar + 8 * jh;
                const int col = aq * 2 + jb;
                const int n   = uBase + col;
                const float pv = jb ? preu2[jh].y : preu2[jh].x;
                const float bv = jb ? bureg.y : bureg.x;
                const float u  = fast_tanh(acc2[j] + bv + pv);
                const float ig = iof_s[0 * (NB * UCOLS) + b * UCOLS + col];
                const float og = iof_s[1 * (NB * UCOLS) + b * UCOLS + col];
                const float fg = iof_s[2 * (NB * UCOLS) + b * UCOLS + col];
                const float cn = ig * u + fg * c_s[b * UCOLS + col];
                c_s[b * UCOLS + col] = cn;
                const float hv = og * fast_tanh(cn);
                out[(size_t)t * NB * H + b * H + n] = hv;
                if (t == SEQ - 1) {
                    out[(size_t)SEQ * NB * H + b * H + n] = hv;               // h_n
                    out[(size_t)SEQ * NB * H + NB * H + b * H + n] = cn;      // c_n
                }
            }
        }
        grid_barrier(bar_target); bar_target += NCTA;
    }
}

__global__ void init_kernel() {
    if (threadIdx.x == 0 && blockIdx.x == 0) g_bar = 0u;
}

extern "C" void kernel_launch(void* const* d_in, const int* in_sizes, int n_in,
                              void* d_out, int out_size) {
    (void)in_sizes; (void)n_in; (void)out_size;
    const float* X   = (const float*)d_in[0];
    const float* Wx  = (const float*)d_in[1];
    const float* bx  = (const float*)d_in[2];
    const float* Wh  = (const float*)d_in[3];
    const float* bh  = (const float*)d_in[4];
    const float* Wum = (const float*)d_in[5];
    const float* bum = (const float*)d_in[6];
    float* out = (float*)d_out;

    static_assert(SMEM_WORDS * 4 == 217728, "smem layout");
    cudaFuncSetAttribute(lstm_kernel, cudaFuncAttributeMaxDynamicSharedMemorySize,
                         SMEM_WORDS * 4);

    init_kernel<<<1, 32>>>();
    pre_kernel<<<dim3(NPRE / 128, (SEQ * NB) / 128), 256>>>(X, Wx, bx);
    lstm_kernel<<<NCTA, 256, SMEM_WORDS * 4>>>(Wh, bh, Wum, bum, out);
}